// round 1
// baseline (speedup 1.0000x reference)
#include <cuda_runtime.h>
#include <cuda_bf16.h>

#define TPB   256
#define QPT   4
#define QTILE (TPB * QPT)   // 1024 queries per block
#define RTILE 1024          // refs per block (16 KB smem as float4)

// Scratch: encoded per-query min for each direction. Max 65536 entries each.
__device__ unsigned g_minEnc[2][65536];

__device__ __forceinline__ unsigned encodeF(float f) {
    unsigned u = __float_as_uint(f);
    return (u & 0x80000000u) ? ~u : (u | 0x80000000u);
}
__device__ __forceinline__ float decodeF(unsigned k) {
    unsigned u = (k & 0x80000000u) ? (k ^ 0x80000000u) : ~k;
    return __uint_as_float(u);
}

__global__ void init_kernel(int n0, int n1) {
    int i = blockIdx.x * blockDim.x + threadIdx.x;
    if (i < n0) g_minEnc[0][i] = 0xFFFFFFFFu;
    if (i < n1) g_minEnc[1][i] = 0xFFFFFFFFu;
}

// grid: (ceil(maxN/QTILE), ceil(maxN/RTILE), 2*B)
__global__ __launch_bounds__(TPB) void chamfer_kernel(
    const float* __restrict__ p1, const float* __restrict__ p2,
    int B, int N, int M)
{
    const int dir = blockIdx.z / B;
    const int b   = blockIdx.z % B;

    const float* q; const float* r; int nq, nr; unsigned* minEnc;
    if (dir == 0) {
        q = p1 + (size_t)b * N * 3; r = p2 + (size_t)b * M * 3;
        nq = N; nr = M; minEnc = &g_minEnc[0][(size_t)b * N];
    } else {
        q = p2 + (size_t)b * M * 3; r = p1 + (size_t)b * N * 3;
        nq = M; nr = N; minEnc = &g_minEnc[1][(size_t)b * M];
    }

    __shared__ float4 sref[RTILE];
    const int rbase = blockIdx.y * RTILE;
    for (int j = threadIdx.x; j < RTILE; j += TPB) {
        int rj = rbase + j;
        float4 v;
        if (rj < nr) {
            float x = r[rj * 3 + 0];
            float y = r[rj * 3 + 1];
            float z = r[rj * 3 + 2];
            v = make_float4(x, y, z, 0.5f * (x * x + y * y + z * z));
        } else {
            v = make_float4(0.f, 0.f, 0.f, __int_as_float(0x7F800000)); // +inf -> never the min
        }
        sref[j] = v;
    }
    __syncthreads();

    const int qbase = blockIdx.x * QTILE + threadIdx.x;
    float qx[QPT], qy[QPT], qz[QPT], mn[QPT];
#pragma unroll
    for (int k = 0; k < QPT; k++) {
        int qi = qbase + k * TPB;
        if (qi < nq) {
            qx[k] = q[qi * 3 + 0];
            qy[k] = q[qi * 3 + 1];
            qz[k] = q[qi * 3 + 2];
        } else {
            qx[k] = qy[k] = qz[k] = 0.f;
        }
        mn[k] = __int_as_float(0x7F800000);
    }

    // Main loop: per (j,k) pair -> 3 FFMA + 1 FMNMX. s = 0.5*||r||^2 - q.r
#pragma unroll 4
    for (int j = 0; j < RTILE; j++) {
        float4 v = sref[j];
#pragma unroll
        for (int k = 0; k < QPT; k++) {
            float s = fmaf(-v.x, qx[k],
                      fmaf(-v.y, qy[k],
                      fmaf(-v.z, qz[k], v.w)));
            mn[k] = fminf(mn[k], s);
        }
    }

#pragma unroll
    for (int k = 0; k < QPT; k++) {
        int qi = qbase + k * TPB;
        if (qi < nq) atomicMin(&minEnc[qi], encodeF(mn[k]));
    }
}

__global__ void reduce_kernel(const float* __restrict__ p1, const float* __restrict__ p2,
                              int B, int N, int M, float* __restrict__ out)
{
    __shared__ float ssum[256];
    float acc = 0.f;

    const int total1 = B * N;
    const float inv1 = 1.0f / (float)total1;
    for (int i = threadIdx.x; i < total1; i += blockDim.x) {
        float x = p1[i * 3 + 0], y = p1[i * 3 + 1], z = p1[i * 3 + 2];
        float d = fmaf(2.f, decodeF(g_minEnc[0][i]), x * x + y * y + z * z);
        acc += fmaxf(d, 0.f) * inv1;
    }

    const int total2 = B * M;
    const float inv2 = 1.0f / (float)total2;
    for (int i = threadIdx.x; i < total2; i += blockDim.x) {
        float x = p2[i * 3 + 0], y = p2[i * 3 + 1], z = p2[i * 3 + 2];
        float d = fmaf(2.f, decodeF(g_minEnc[1][i]), x * x + y * y + z * z);
        acc += fmaxf(d, 0.f) * inv2;
    }

    ssum[threadIdx.x] = acc;
    __syncthreads();
    for (int s = blockDim.x / 2; s > 0; s >>= 1) {
        if (threadIdx.x < s) ssum[threadIdx.x] += ssum[threadIdx.x + s];
        __syncthreads();
    }
    if (threadIdx.x == 0) out[0] = ssum[0];
}

extern "C" void kernel_launch(void* const* d_in, const int* in_sizes, int n_in,
                              void* d_out, int out_size)
{
    const float* p1 = (const float*)d_in[0];
    const float* p2 = (const float*)d_in[1];

    const int B = 4;
    const int N = in_sizes[0] / (B * 3);
    const int M = in_sizes[1] / (B * 3);

    const int n0 = B * N, n1 = B * M;
    const int mx = n0 > n1 ? n0 : n1;
    init_kernel<<<(mx + 255) / 256, 256>>>(n0, n1);

    const int maxNM = N > M ? N : M;
    dim3 grid((maxNM + QTILE - 1) / QTILE,
              (maxNM + RTILE - 1) / RTILE,
              2 * B);
    chamfer_kernel<<<grid, TPB>>>(p1, p2, B, N, M);

    reduce_kernel<<<1, 256>>>(p1, p2, B, N, M, (float*)d_out);
}

// round 2
// speedup vs baseline: 1.9161x; 1.9161x over previous
#include <cuda_runtime.h>
#include <cuda_bf16.h>

#define TPB   256
#define QPT   4
#define QTILE (TPB * QPT)   // 1024 queries per block
#define RTILE 512           // refs per block tile (256 packed pairs, 8 KB smem)
#define RPAIR (RTILE / 2)

// Scratch: encoded per-query min for each direction.
__device__ unsigned g_minEnc[2][65536];

__device__ __forceinline__ unsigned encodeF(float f) {
    unsigned u = __float_as_uint(f);
    return (u & 0x80000000u) ? ~u : (u | 0x80000000u);
}
__device__ __forceinline__ float decodeF(unsigned k) {
    unsigned u = (k & 0x80000000u) ? (k ^ 0x80000000u) : ~k;
    return __uint_as_float(u);
}

// ---- packed f32x2 helpers (Blackwell sm_100+) ----
__device__ __forceinline__ unsigned long long pk2(float lo, float hi) {
    unsigned long long v;
    asm("mov.b64 %0, {%1, %2};" : "=l"(v) : "f"(lo), "f"(hi));
    return v;
}
__device__ __forceinline__ unsigned long long fma2(unsigned long long a,
                                                   unsigned long long b,
                                                   unsigned long long c) {
    unsigned long long d;
    asm("fma.rn.f32x2 %0, %1, %2, %3;" : "=l"(d) : "l"(a), "l"(b), "l"(c));
    return d;
}
__device__ __forceinline__ void unpk2(unsigned long long v, float& lo, float& hi) {
    asm("mov.b64 {%0, %1}, %2;" : "=f"(lo), "=f"(hi) : "l"(v));
}

__global__ void init_kernel(int n0, int n1, float* out) {
    int i = blockIdx.x * blockDim.x + threadIdx.x;
    if (i < n0) g_minEnc[0][i] = 0xFFFFFFFFu;
    if (i < n1) g_minEnc[1][i] = 0xFFFFFFFFu;
    if (i == 0) out[0] = 0.0f;
}

// grid: (ceil(maxN/QTILE), ceil(maxN/RTILE), 2*B)
__global__ __launch_bounds__(TPB) void chamfer_kernel(
    const float* __restrict__ p1, const float* __restrict__ p2,
    int B, int N, int M)
{
    const int dir = blockIdx.z / B;
    const int b   = blockIdx.z % B;

    const float* q; const float* r; int nq, nr; unsigned* minEnc;
    if (dir == 0) {
        q = p1 + (size_t)b * N * 3; r = p2 + (size_t)b * M * 3;
        nq = N; nr = M; minEnc = &g_minEnc[0][(size_t)b * N];
    } else {
        q = p2 + (size_t)b * M * 3; r = p1 + (size_t)b * N * 3;
        nq = M; nr = N; minEnc = &g_minEnc[1][(size_t)b * M];
    }

    // Packed ref tiles: sA[p] = {x0,x1 | y0,y1}, sB[p] = {z0,z1 | w0,w1}
    // where w = 0.5*||r||^2. Read back as ulonglong2 -> zero-cost packed regs.
    __shared__ float4 sA[RPAIR];
    __shared__ float4 sB[RPAIR];

    const int rbase = blockIdx.y * RTILE;
    for (int p = threadIdx.x; p < RPAIR; p += TPB) {
        int r0 = rbase + 2 * p;
        int r1 = r0 + 1;
        float x0 = 0.f, y0 = 0.f, z0 = 0.f, w0 = __int_as_float(0x7F800000);
        float x1 = 0.f, y1 = 0.f, z1 = 0.f, w1 = __int_as_float(0x7F800000);
        if (r0 < nr) {
            x0 = r[r0 * 3 + 0]; y0 = r[r0 * 3 + 1]; z0 = r[r0 * 3 + 2];
            w0 = 0.5f * (x0 * x0 + y0 * y0 + z0 * z0);
        }
        if (r1 < nr) {
            x1 = r[r1 * 3 + 0]; y1 = r[r1 * 3 + 1]; z1 = r[r1 * 3 + 2];
            w1 = 0.5f * (x1 * x1 + y1 * y1 + z1 * z1);
        }
        sA[p] = make_float4(x0, x1, y0, y1);
        sB[p] = make_float4(z0, z1, w0, w1);
    }
    __syncthreads();

    const int qbase = blockIdx.x * QTILE + threadIdx.x;
    unsigned long long nqx[QPT], nqy[QPT], nqz[QPT];
    float mnA[QPT], mnB[QPT];
#pragma unroll
    for (int k = 0; k < QPT; k++) {
        int qi = qbase + k * TPB;
        float x = 0.f, y = 0.f, z = 0.f;
        if (qi < nq) {
            x = q[qi * 3 + 0]; y = q[qi * 3 + 1]; z = q[qi * 3 + 2];
        }
        nqx[k] = pk2(-x, -x);
        nqy[k] = pk2(-y, -y);
        nqz[k] = pk2(-z, -z);
        mnA[k] = __int_as_float(0x7F800000);
        mnB[k] = __int_as_float(0x7F800000);
    }

    const ulonglong2* __restrict__ pA = (const ulonglong2*)sA;
    const ulonglong2* __restrict__ pB = (const ulonglong2*)sB;

    // Per packed pair & query: s2 = fma2(rx2,-qx2, fma2(ry2,-qy2, fma2(rz2,-qz2, rw2)))
    // 3 FFMA2 (fma pipe) + 2 FMNMX (alu pipe) per 2 point-pairs.
#pragma unroll 4
    for (int p = 0; p < RPAIR; p++) {
        ulonglong2 a = pA[p];   // a.x = {x0,x1}, a.y = {y0,y1}
        ulonglong2 c = pB[p];   // c.x = {z0,z1}, c.y = {w0,w1}
#pragma unroll
        for (int k = 0; k < QPT; k++) {
            unsigned long long s = fma2(a.x, nqx[k],
                                   fma2(a.y, nqy[k],
                                   fma2(c.x, nqz[k], c.y)));
            float lo, hi;
            unpk2(s, lo, hi);
            mnA[k] = fminf(mnA[k], lo);
            mnB[k] = fminf(mnB[k], hi);
        }
    }

#pragma unroll
    for (int k = 0; k < QPT; k++) {
        int qi = qbase + k * TPB;
        if (qi < nq) {
            float mn = fminf(mnA[k], mnB[k]);
            atomicMin(&minEnc[qi], encodeF(mn));
        }
    }
}

// Parallel reduce: grid-stride over both directions, block-partial -> atomicAdd.
__global__ void reduce_kernel(const float* __restrict__ p1, const float* __restrict__ p2,
                              int B, int N, int M, float* __restrict__ out)
{
    __shared__ float ssum[256];
    const int total1 = B * N;
    const int total2 = B * M;
    const float inv1 = 1.0f / (float)total1;
    const float inv2 = 1.0f / (float)total2;
    const int total = total1 + total2;

    float acc = 0.f;
    for (int i = blockIdx.x * blockDim.x + threadIdx.x; i < total;
         i += gridDim.x * blockDim.x) {
        float x, y, z, mn, inv;
        if (i < total1) {
            x = p1[i * 3 + 0]; y = p1[i * 3 + 1]; z = p1[i * 3 + 2];
            mn = decodeF(g_minEnc[0][i]); inv = inv1;
        } else {
            int j = i - total1;
            x = p2[j * 3 + 0]; y = p2[j * 3 + 1]; z = p2[j * 3 + 2];
            mn = decodeF(g_minEnc[1][j]); inv = inv2;
        }
        float d = fmaf(2.f, mn, x * x + y * y + z * z);
        acc += fmaxf(d, 0.f) * inv;
    }

    ssum[threadIdx.x] = acc;
    __syncthreads();
    for (int s = blockDim.x / 2; s > 0; s >>= 1) {
        if (threadIdx.x < s) ssum[threadIdx.x] += ssum[threadIdx.x + s];
        __syncthreads();
    }
    if (threadIdx.x == 0) atomicAdd(out, ssum[0]);
}

extern "C" void kernel_launch(void* const* d_in, const int* in_sizes, int n_in,
                              void* d_out, int out_size)
{
    const float* p1 = (const float*)d_in[0];
    const float* p2 = (const float*)d_in[1];

    const int B = 4;
    const int N = in_sizes[0] / (B * 3);
    const int M = in_sizes[1] / (B * 3);

    const int n0 = B * N, n1 = B * M;
    const int mx = n0 > n1 ? n0 : n1;
    init_kernel<<<(mx + 255) / 256, 256>>>(n0, n1, (float*)d_out);

    const int maxNM = N > M ? N : M;
    dim3 grid((maxNM + QTILE - 1) / QTILE,
              (maxNM + RTILE - 1) / RTILE,
              2 * B);
    chamfer_kernel<<<grid, TPB>>>(p1, p2, B, N, M);

    reduce_kernel<<<64, 256>>>(p1, p2, B, N, M, (float*)d_out);
}

// round 4
// speedup vs baseline: 1.9219x; 1.0030x over previous
#include <cuda_runtime.h>
#include <cuda_bf16.h>

#define TPB   256
#define QPT   4
#define QTILE (TPB * QPT)   // 1024 queries per block
#define RTILE 512           // refs per block tile (256 packed pairs, 8 KB smem)
#define RPAIR (RTILE / 2)

// Scratch: encoded per-query min for each direction.
__device__ unsigned g_minEnc[2][65536];

__device__ __forceinline__ unsigned encodeF(float f) {
    unsigned u = __float_as_uint(f);
    return (u & 0x80000000u) ? ~u : (u | 0x80000000u);
}
__device__ __forceinline__ float decodeF(unsigned k) {
    unsigned u = (k & 0x80000000u) ? (k ^ 0x80000000u) : ~k;
    return __uint_as_float(u);
}

// ---- packed f32x2 helpers (Blackwell sm_100+) ----
__device__ __forceinline__ unsigned long long pk2(float lo, float hi) {
    unsigned long long v;
    asm("mov.b64 %0, {%1, %2};" : "=l"(v) : "f"(lo), "f"(hi));
    return v;
}
__device__ __forceinline__ unsigned long long fma2(unsigned long long a,
                                                   unsigned long long b,
                                                   unsigned long long c) {
    unsigned long long d;
    asm("fma.rn.f32x2 %0, %1, %2, %3;" : "=l"(d) : "l"(a), "l"(b), "l"(c));
    return d;
}
__device__ __forceinline__ void unpk2(unsigned long long v, float& lo, float& hi) {
    asm("mov.b64 {%0, %1}, %2;" : "=f"(lo), "=f"(hi) : "l"(v));
}

__global__ void init_kernel(int n0, int n1, float* out) {
    int i = blockIdx.x * blockDim.x + threadIdx.x;
    if (i < n0) g_minEnc[0][i] = 0xFFFFFFFFu;
    if (i < n1) g_minEnc[1][i] = 0xFFFFFFFFu;
    if (i == 0) out[0] = 0.0f;
}

// grid: (ceil(maxN/QTILE), ceil(maxN/RTILE), 2*B)
__global__ __launch_bounds__(TPB) void chamfer_kernel(
    const float* __restrict__ p1, const float* __restrict__ p2,
    int B, int N, int M)
{
    const int dir = blockIdx.z / B;
    const int b   = blockIdx.z % B;

    const float* q; const float* r; int nq, nr; unsigned* minEnc;
    if (dir == 0) {
        q = p1 + (size_t)b * N * 3; r = p2 + (size_t)b * M * 3;
        nq = N; nr = M; minEnc = &g_minEnc[0][(size_t)b * N];
    } else {
        q = p2 + (size_t)b * M * 3; r = p1 + (size_t)b * N * 3;
        nq = M; nr = N; minEnc = &g_minEnc[1][(size_t)b * M];
    }

    // Packed ref tiles: sA[p] = {x0,x1 | y0,y1}, sB[p] = {z0,z1 | w0,w1}
    // where w = 0.5*||r||^2. Read back as ulonglong2 -> packed 64-bit regs.
    __shared__ float4 sA[RPAIR];
    __shared__ float4 sB[RPAIR];

    const int rbase = blockIdx.y * RTILE;
    for (int p = threadIdx.x; p < RPAIR; p += TPB) {
        int r0 = rbase + 2 * p;
        int r1 = r0 + 1;
        float x0 = 0.f, y0 = 0.f, z0 = 0.f, w0 = __int_as_float(0x7F800000);
        float x1 = 0.f, y1 = 0.f, z1 = 0.f, w1 = __int_as_float(0x7F800000);
        if (r0 < nr) {
            x0 = r[r0 * 3 + 0]; y0 = r[r0 * 3 + 1]; z0 = r[r0 * 3 + 2];
            w0 = 0.5f * (x0 * x0 + y0 * y0 + z0 * z0);
        }
        if (r1 < nr) {
            x1 = r[r1 * 3 + 0]; y1 = r[r1 * 3 + 1]; z1 = r[r1 * 3 + 2];
            w1 = 0.5f * (x1 * x1 + y1 * y1 + z1 * z1);
        }
        sA[p] = make_float4(x0, x1, y0, y1);
        sB[p] = make_float4(z0, z1, w0, w1);
    }
    __syncthreads();

    const int qbase = blockIdx.x * QTILE + threadIdx.x;
    unsigned long long nqx[QPT], nqy[QPT], nqz[QPT];
    float mnA[QPT], mnB[QPT];
#pragma unroll
    for (int k = 0; k < QPT; k++) {
        int qi = qbase + k * TPB;
        float x = 0.f, y = 0.f, z = 0.f;
        if (qi < nq) {
            x = q[qi * 3 + 0]; y = q[qi * 3 + 1]; z = q[qi * 3 + 2];
        }
        nqx[k] = pk2(-x, -x);
        nqy[k] = pk2(-y, -y);
        nqz[k] = pk2(-z, -z);
        mnA[k] = __int_as_float(0x7F800000);
        mnB[k] = __int_as_float(0x7F800000);
    }

    const ulonglong2* __restrict__ pA = (const ulonglong2*)sA;
    const ulonglong2* __restrict__ pB = (const ulonglong2*)sB;

    // Stage-major inner loop: consecutive FFMA2s at the same chain depth share
    // the ref operand (a.x / a.y / c.x / c.y), engaging the operand-reuse cache
    // and cutting distinct RF-bank reads per issue (rt 3 -> 2).
#pragma unroll 4
    for (int p = 0; p < RPAIR; p++) {
        ulonglong2 a = pA[p];   // a.x = {x0,x1}, a.y = {y0,y1}
        ulonglong2 c = pB[p];   // c.x = {z0,z1}, c.y = {w0,w1}
        unsigned long long t[QPT];
#pragma unroll
        for (int k = 0; k < QPT; k++) t[k] = fma2(c.x, nqz[k], c.y);
#pragma unroll
        for (int k = 0; k < QPT; k++) t[k] = fma2(a.y, nqy[k], t[k]);
#pragma unroll
        for (int k = 0; k < QPT; k++) t[k] = fma2(a.x, nqx[k], t[k]);
#pragma unroll
        for (int k = 0; k < QPT; k++) {
            float lo, hi;
            unpk2(t[k], lo, hi);
            mnA[k] = fminf(mnA[k], lo);
            mnB[k] = fminf(mnB[k], hi);
        }
    }

#pragma unroll
    for (int k = 0; k < QPT; k++) {
        int qi = qbase + k * TPB;
        if (qi < nq) {
            atomicMin(&minEnc[qi], encodeF(fminf(mnA[k], mnB[k])));
        }
    }
}

// Parallel reduce: grid-stride over both directions, block-partial -> atomicAdd.
__global__ void reduce_kernel(const float* __restrict__ p1, const float* __restrict__ p2,
                              int B, int N, int M, float* __restrict__ out)
{
    __shared__ float ssum[256];
    const int total1 = B * N;
    const int total2 = B * M;
    const float inv1 = 1.0f / (float)total1;
    const float inv2 = 1.0f / (float)total2;
    const int total = total1 + total2;

    float acc = 0.f;
    for (int i = blockIdx.x * blockDim.x + threadIdx.x; i < total;
         i += gridDim.x * blockDim.x) {
        float x, y, z, mn, inv;
        if (i < total1) {
            x = p1[i * 3 + 0]; y = p1[i * 3 + 1]; z = p1[i * 3 + 2];
            mn = decodeF(g_minEnc[0][i]); inv = inv1;
        } else {
            int j = i - total1;
            x = p2[j * 3 + 0]; y = p2[j * 3 + 1]; z = p2[j * 3 + 2];
            mn = decodeF(g_minEnc[1][j]); inv = inv2;
        }
        float d = fmaf(2.f, mn, x * x + y * y + z * z);
        acc += fmaxf(d, 0.f) * inv;
    }

    ssum[threadIdx.x] = acc;
    __syncthreads();
    for (int s = blockDim.x / 2; s > 0; s >>= 1) {
        if (threadIdx.x < s) ssum[threadIdx.x] += ssum[threadIdx.x + s];
        __syncthreads();
    }
    if (threadIdx.x == 0) atomicAdd(out, ssum[0]);
}

extern "C" void kernel_launch(void* const* d_in, const int* in_sizes, int n_in,
                              void* d_out, int out_size)
{
    const float* p1 = (const float*)d_in[0];
    const float* p2 = (const float*)d_in[1];

    const int B = 4;
    const int N = in_sizes[0] / (B * 3);
    const int M = in_sizes[1] / (B * 3);

    const int n0 = B * N, n1 = B * M;
    const int mx = n0 > n1 ? n0 : n1;
    init_kernel<<<(mx + 255) / 256, 256>>>(n0, n1, (float*)d_out);

    const int maxNM = N > M ? N : M;
    dim3 grid((maxNM + QTILE - 1) / QTILE,
              (maxNM + RTILE - 1) / RTILE,
              2 * B);
    chamfer_kernel<<<grid, TPB>>>(p1, p2, B, N, M);

    reduce_kernel<<<64, 256>>>(p1, p2, B, N, M, (float*)d_out);
}